// round 11
// baseline (speedup 1.0000x reference)
#include <cuda_runtime.h>
#include <cuda_fp16.h>
#include <stdint.h>
#include <math.h>

#define NTOK 8192          // B*S
#define DM 1024
#define DE 512
#define NE 8

// ---------------- scratch (device globals) ----------------
__device__ int   g_count[NE];
__device__ int   g_tok [NE * NTOK];
__device__ float g_gate[NE * NTOK];
__device__ __half g_x_hi[(size_t)NTOK * DM];
__device__ __half g_x_lo[(size_t)NTOK * DM];
__device__ __half g_h_hi[(size_t)NE * NTOK * DE];
__device__ __half g_h_lo[(size_t)NE * NTOK * DE];
__device__ __half g_w1t[(size_t)NE * DE * DM];   // [e][n][k] k-major, fp16
__device__ __half g_w2t[(size_t)NE * DM * DE];   // [e][n][k] fp16

// ---------------- helpers ----------------
static __device__ __forceinline__ uint32_t smem_u32(const void* p) {
    uint32_t a;
    asm("{ .reg .u64 t; cvta.to.shared.u64 t, %1; cvt.u32.u64 %0, t; }"
        : "=r"(a) : "l"(p));
    return a;
}

static __device__ __forceinline__ void cpa16(uint32_t dst, const void* src) {
    asm volatile("cp.async.cg.shared.global [%0], [%1], 16;" :: "r"(dst), "l"(src));
}
#define CP_COMMIT() asm volatile("cp.async.commit_group;" ::: "memory")
#define CP_WAIT1()  asm volatile("cp.async.wait_group 1;" ::: "memory")

#define LDMX4(r0, r1, r2, r3, addr)                                          \
    asm volatile("ldmatrix.sync.aligned.m8n8.x4.shared.b16 {%0,%1,%2,%3}, [%4];" \
        : "=r"(r0), "=r"(r1), "=r"(r2), "=r"(r3) : "r"(addr))

#define MMA(ac, a, b)                                                        \
    asm volatile("mma.sync.aligned.m16n8k16.row.col.f32.f16.f16.f32 "        \
        "{%0,%1,%2,%3}, {%4,%5,%6,%7}, {%8,%9}, {%0,%1,%2,%3};"              \
        : "+f"((ac)[0]), "+f"((ac)[1]), "+f"((ac)[2]), "+f"((ac)[3])         \
        : "r"((a)[0]), "r"((a)[1]), "r"((a)[2]), "r"((a)[3]),                \
          "r"((b)[0]), "r"((b)[1]))

static __device__ __forceinline__ void split1h(float v, unsigned& h, unsigned& l) {
    __half hh = __float2half_rn(v);
    float r = v - __half2float(hh);
    __half hl = __float2half_rn(r);
    h = (unsigned)__half_as_ushort(hh);
    l = (unsigned)__half_as_ushort(hl);
}

// ============================================================
// 0) zero output + counters
// ============================================================
__global__ void zero_kernel(float* __restrict__ out) {
    int idx = blockIdx.x * blockDim.x + threadIdx.x;
    ((float4*)out)[idx] = make_float4(0.f, 0.f, 0.f, 0.f);
    if (blockIdx.x == 0 && threadIdx.x < NE) g_count[threadIdx.x] = 0;
}

// ============================================================
// 1) merged prep: x-split (fp16 hi/lo) + w1/w2 transpose to fp16
// ============================================================
#define XB 8192
__global__ void prep_all(const float* __restrict__ x,
                         const float* __restrict__ w1,
                         const float* __restrict__ w2) {
    __shared__ float t[32][33];
    int b = blockIdx.x, tid = threadIdx.x;

    if (b < XB) {
        size_t i = (size_t)b * 256 + tid;   // float4 index
        float4 v = ((const float4*)x)[i];
        unsigned h0, l0, h1, l1, h2, l2, h3, l3;
        split1h(v.x, h0, l0); split1h(v.y, h1, l1);
        split1h(v.z, h2, l2); split1h(v.w, h3, l3);
        ((uint2*)g_x_hi)[i] = make_uint2(h0 | (h1 << 16), h2 | (h3 << 16));
        ((uint2*)g_x_lo)[i] = make_uint2(l0 | (l1 << 16), l2 | (l3 << 16));
        return;
    }

    const float* in;
    __half* outp;
    int K, N, nblk;
    if (b < XB + 4096) { b -= XB;        in = w1; outp = g_w1t; K = DM; N = DE; nblk = 16; }
    else               { b -= XB + 4096; in = w2; outp = g_w2t; K = DE; N = DM; nblk = 32; }

    int per_e = nblk * (K / 32);
    int e   = b / per_e;
    int rem = b % per_e;
    int n0  = (rem % nblk) * 32;
    int k0  = (rem / nblk) * 32;
    int tx  = tid & 31, ty = tid >> 5;

    const float* pin = in + (size_t)e * K * N;
#pragma unroll
    for (int i = 0; i < 4; i++)
        t[ty + i * 8][tx] = pin[(size_t)(k0 + ty + i * 8) * N + n0 + tx];
    __syncthreads();
#pragma unroll
    for (int i = 0; i < 4; i++) {
        int nl = ty + i * 8, kl = tx;
        outp[((size_t)e * N + n0 + nl) * K + k0 + kl] = __float2half_rn(t[kl][nl]);
    }
}

// ============================================================
// 2) routing: one warp per token
// ============================================================
__global__ void route_kernel(const float* __restrict__ x,
                             const float* __restrict__ centroids,
                             const float* __restrict__ w_route) {
    int gwarp = (blockIdx.x * blockDim.x + threadIdx.x) >> 5;
    int lane  = threadIdx.x & 31;
    if (gwarp >= NTOK) return;
    int tok = gwarp;

    const float4* xr = (const float4*)(x + (size_t)tok * DM);
    float4 xv[8];
#pragma unroll
    for (int u = 0; u < 8; u++) xv[u] = xr[u * 32 + lane];

    float nx = 0.f;
#pragma unroll
    for (int u = 0; u < 8; u++) {
        float4 v = xv[u];
        nx += v.x * v.x + v.y * v.y + v.z * v.z + v.w * v.w;
    }
#pragma unroll
    for (int off = 16; off; off >>= 1) nx += __shfl_xor_sync(0xffffffffu, nx, off);
    float xn = fmaxf(sqrtf(nx), 1e-12f);

    float logits[NE];
#pragma unroll
    for (int e = 0; e < NE; e++) {
        const float4* cr = (const float4*)(centroids + (size_t)e * DM);
        const float4* wr = (const float4*)(w_route   + (size_t)e * DM);
        float sc = 0.f, scc = 0.f, sr = 0.f;
#pragma unroll
        for (int u = 0; u < 8; u++) {
            float4 c = cr[u * 32 + lane];
            float4 w = wr[u * 32 + lane];
            float4 v = xv[u];
            sc  += v.x * c.x + v.y * c.y + v.z * c.z + v.w * c.w;
            scc += c.x * c.x + c.y * c.y + c.z * c.z + c.w * c.w;
            sr  += v.x * w.x + v.y * w.y + v.z * w.z + v.w * w.w;
        }
#pragma unroll
        for (int off = 16; off; off >>= 1) {
            sc  += __shfl_xor_sync(0xffffffffu, sc,  off);
            scc += __shfl_xor_sync(0xffffffffu, scc, off);
            sr  += __shfl_xor_sync(0xffffffffu, sr,  off);
        }
        float cn = fmaxf(sqrtf(scc), 1e-12f);
        logits[e] = sc / (xn * cn) + sr;
    }

    if (lane == 0) {
        int e1 = 0; float l1 = logits[0];
#pragma unroll
        for (int e = 1; e < NE; e++) if (logits[e] > l1) { l1 = logits[e]; e1 = e; }
        int e2 = -1; float l2 = -INFINITY;
#pragma unroll
        for (int e = 0; e < NE; e++) if (e != e1 && logits[e] > l2) { l2 = logits[e]; e2 = e; }
        float b  = expf(l2 - l1);
        float g1 = 1.f / (1.f + b);
        float g2 = b  / (1.f + b);
        int p1 = atomicAdd(&g_count[e1], 1);
        g_tok [e1 * NTOK + p1] = tok;
        g_gate[e1 * NTOK + p1] = g1;
        int p2 = atomicAdd(&g_count[e2], 1);
        g_tok [e2 * NTOK + p2] = tok;
        g_gate[e2 * NTOK + p2] = g2;
    }
}

// ============================================================
// GEMM geometry: block 128x128, BK=32, 8 warps (2x4), warp 64x32
// fp16 2-term split: acc += Ahi*B + Alo*B
// 3-stage ring, ONE __syncthreads per chunk:
//   wait(1); sync; compute(sc); load(sc+2); commit
// ============================================================
#define BK 32
#define SROWB 80
#define TILE_B (128 * SROWB)          // 10240 B
#define STAGE_B (3 * TILE_B)          // 30720 B
#define DYN_SMEM (3 * STAGE_B)        // 92160 B, 2 CTA/SM

#define MMA_KSTEP(sb)                                                        \
    do {                                                                     \
        uint32_t ah[4][4], bh[4][2];                                         \
        _Pragma("unroll")                                                    \
        for (int mt = 0; mt < 4; mt++) {                                     \
            uint32_t aa = (sb) + a_off + mt * 16 * SROWB + ks * 32;          \
            LDMX4(ah[mt][0], ah[mt][1], ah[mt][2], ah[mt][3], aa);           \
        }                                                                    \
        _Pragma("unroll")                                                    \
        for (int p = 0; p < 2; p++) {                                        \
            uint32_t ba = (sb) + 2 * TILE_B + b_off + p * 16 * SROWB + ks * 32; \
            uint32_t t0, t1, t2, t3;                                         \
            LDMX4(t0, t1, t2, t3, ba);                                       \
            bh[2 * p][0] = t0; bh[2 * p][1] = t1;                            \
            bh[2 * p + 1][0] = t2; bh[2 * p + 1][1] = t3;                    \
        }                                                                    \
        _Pragma("unroll")                                                    \
        for (int mt = 0; mt < 4; mt++)                                       \
            _Pragma("unroll")                                                \
            for (int nt = 0; nt < 4; nt++) MMA(acc[mt][nt], ah[mt], bh[nt]); \
        uint32_t al[4][4];                                                   \
        _Pragma("unroll")                                                    \
        for (int mt = 0; mt < 4; mt++) {                                     \
            uint32_t aa = (sb) + TILE_B + a_off + mt * 16 * SROWB + ks * 32; \
            LDMX4(al[mt][0], al[mt][1], al[mt][2], al[mt][3], aa);           \
        }                                                                    \
        _Pragma("unroll")                                                    \
        for (int mt = 0; mt < 4; mt++)                                       \
            _Pragma("unroll")                                                \
            for (int nt = 0; nt < 4; nt++) MMA(acc[mt][nt], al[mt], bh[nt]); \
    } while (0)

// ============================================================
// 3) FF1: h = gelu(gather(x) @ w1[e] + b1[e])
// ============================================================
__global__ __launch_bounds__(256, 2) void ff1_mma(const float* __restrict__ b1) {
    extern __shared__ char dsm[];
    __shared__ int rows_s[128];

    int e   = blockIdx.z;
    int cnt = g_count[e];
    int m0  = blockIdx.x * 128;
    if (m0 >= cnt) return;
    int n0  = blockIdx.y * 128;
    int tid = threadIdx.x, lane = tid & 31, wid = tid >> 5;
    int warpM = wid >> 2, warpN = wid & 3;

    if (tid < 128) {
        int m = m0 + tid;
        rows_s[tid] = (m < cnt) ? g_tok[e * NTOK + m] : 0;
    }
    __syncthreads();

    uint32_t sbase = smem_u32(dsm);

    int arow = lane & 15;
    int akad = (lane >> 4) << 3;
    int brow = ((lane & 16) >> 1) | (lane & 7);
    int bkad = lane & 8;
    uint32_t a_off = (uint32_t)((warpM * 64 + arow) * SROWB + akad * 2);
    uint32_t b_off = (uint32_t)((warpN * 32 + brow) * SROWB + bkad * 2);

    float acc[4][4][4];
#pragma unroll
    for (int mt = 0; mt < 4; mt++)
#pragma unroll
        for (int nt = 0; nt < 4; nt++)
#pragma unroll
            for (int q = 0; q < 4; q++) acc[mt][nt][q] = 0.f;

    const int NC = DM / BK;   // 32

    auto load_stage = [&](int s, int k0) {
        uint32_t sb = sbase + s * STAGE_B;
#pragma unroll
        for (int j = 0; j < 2; j++) {
            int ci  = tid + j * 256;          // 0..511
            int row = ci >> 2, kc = ci & 3;
            uint32_t d0 = sb + row * SROWB + kc * 16;
            size_t ax = (size_t)rows_s[row] * DM + k0 + kc * 8;
            cpa16(d0,              g_x_hi + ax);
            cpa16(d0 + TILE_B,     g_x_lo + ax);
            size_t bx = ((size_t)e * DE + n0 + row) * DM + k0 + kc * 8;
            cpa16(d0 + 2 * TILE_B, g_w1t + bx);
        }
    };

    load_stage(0, 0); CP_COMMIT();
    load_stage(1, BK); CP_COMMIT();

    int sc = 0;
    for (int c = 0; c < NC; c++) {
        CP_WAIT1();
        __syncthreads();
        uint32_t sb = sbase + sc * STAGE_B;
#pragma unroll
        for (int ks = 0; ks < 2; ks++) { MMA_KSTEP(sb); }
        if (c + 2 < NC) {
            int sn = sc + 2; if (sn >= 3) sn -= 3;
            load_stage(sn, (c + 2) * BK);
        }
        CP_COMMIT();
        if (++sc == 3) sc = 0;
    }

    // ---- epilogue: bias + gelu, split to fp16 hi/lo ----
    int r = lane >> 2, cp = (lane & 3) * 2;
#pragma unroll
    for (int mt = 0; mt < 4; mt++)
#pragma unroll
        for (int half = 0; half < 2; half++) {
            int m = m0 + warpM * 64 + mt * 16 + r + half * 8;
            if (m >= cnt) continue;
            size_t base = ((size_t)e * NTOK + m) * DE;
#pragma unroll
            for (int nt = 0; nt < 4; nt++) {
                int nn = n0 + warpN * 32 + nt * 8 + cp;
                float v0 = acc[mt][nt][half * 2 + 0] + b1[e * DE + nn];
                float v1 = acc[mt][nt][half * 2 + 1] + b1[e * DE + nn + 1];
                v0 = 0.5f * v0 * (1.0f + erff(v0 * 0.7071067811865476f));
                v1 = 0.5f * v1 * (1.0f + erff(v1 * 0.7071067811865476f));
                unsigned h0, l0, h1, l1;
                split1h(v0, h0, l0); split1h(v1, h1, l1);
                *(unsigned*)((__half*)g_h_hi + base + nn) = h0 | (h1 << 16);
                *(unsigned*)((__half*)g_h_lo + base + nn) = l0 | (l1 << 16);
            }
        }
}

// ============================================================
// 4) FF2: out[tok] += gate * (h @ w2[e] + b2[e])
// ============================================================
__global__ __launch_bounds__(256, 2) void ff2_mma(const float* __restrict__ b2,
                                                  float* __restrict__ out) {
    extern __shared__ char dsm[];

    int e   = blockIdx.z;
    int cnt = g_count[e];
    int m0  = blockIdx.x * 128;
    if (m0 >= cnt) return;
    int n0  = blockIdx.y * 128;
    int tid = threadIdx.x, lane = tid & 31, wid = tid >> 5;
    int warpM = wid >> 2, warpN = wid & 3;

    uint32_t sbase = smem_u32(dsm);

    int arow = lane & 15;
    int akad = (lane >> 4) << 3;
    int brow = ((lane & 16) >> 1) | (lane & 7);
    int bkad = lane & 8;
    uint32_t a_off = (uint32_t)((warpM * 64 + arow) * SROWB + akad * 2);
    uint32_t b_off = (uint32_t)((warpN * 32 + brow) * SROWB + bkad * 2);

    float acc[4][4][4];
#pragma unroll
    for (int mt = 0; mt < 4; mt++)
#pragma unroll
        for (int nt = 0; nt < 4; nt++)
#pragma unroll
            for (int q = 0; q < 4; q++) acc[mt][nt][q] = 0.f;

    const int NC = DE / BK;   // 16

    auto load_stage = [&](int s, int k0) {
        uint32_t sb = sbase + s * STAGE_B;
#pragma unroll
        for (int j = 0; j < 2; j++) {
            int ci  = tid + j * 256;
            int row = ci >> 2, kc = ci & 3;
            uint32_t d0 = sb + row * SROWB + kc * 16;
            size_t ax = ((size_t)e * NTOK + m0 + row) * DE + k0 + kc * 8;
            cpa16(d0,              g_h_hi + ax);
            cpa16(d0 + TILE_B,     g_h_lo + ax);
            size_t bx = ((size_t)e * DM + n0 + row) * DE + k0 + kc * 8;
            cpa16(d0 + 2 * TILE_B, g_w2t + bx);
        }
    };

    load_stage(0, 0); CP_COMMIT();
    load_stage(1, BK); CP_COMMIT();

    int sc = 0;
    for (int c = 0; c < NC; c++) {
        CP_WAIT1();
        __syncthreads();
        uint32_t sb = sbase + sc * STAGE_B;
#pragma unroll
        for (int ks = 0; ks < 2; ks++) { MMA_KSTEP(sb); }
        if (c + 2 < NC) {
            int sn = sc + 2; if (sn >= 3) sn -= 3;
            load_stage(sn, (c + 2) * BK);
        }
        CP_COMMIT();
        if (++sc == 3) sc = 0;
    }

    // ---- epilogue: gate * (acc + b2) -> atomic add into out ----
    int r = lane >> 2, cp = (lane & 3) * 2;
#pragma unroll
    for (int mt = 0; mt < 4; mt++)
#pragma unroll
        for (int half = 0; half < 2; half++) {
            int m = m0 + warpM * 64 + mt * 16 + r + half * 8;
            if (m >= cnt) continue;
            int   tok  = g_tok [e * NTOK + m];
            float gate = g_gate[e * NTOK + m];
            float* orow = out + (size_t)tok * DM;
#pragma unroll
            for (int nt = 0; nt < 4; nt++) {
                int nn = n0 + warpN * 32 + nt * 8 + cp;
                float v0 = gate * (acc[mt][nt][half * 2 + 0] + b2[e * DM + nn]);
                float v1 = gate * (acc[mt][nt][half * 2 + 1] + b2[e * DM + nn + 1]);
                atomicAdd(&orow[nn],     v0);
                atomicAdd(&orow[nn + 1], v1);
            }
        }
}

// ============================================================
// launcher: zero(1), prep_all(side stream), route, ff1, ff2
// ============================================================
extern "C" void kernel_launch(void* const* d_in, const int* in_sizes, int n_in,
                              void* d_out, int out_size) {
    const float* x         = (const float*)d_in[0];
    const float* w1        = (const float*)d_in[1];
    const float* b1        = (const float*)d_in[2];
    const float* w2        = (const float*)d_in[3];
    const float* b2        = (const float*)d_in[4];
    const float* centroids = (const float*)d_in[5];
    const float* w_route   = (const float*)d_in[6];
    float* out = (float*)d_out;

    static cudaStream_t sA = nullptr;
    static cudaEvent_t evFork, evA;
    if (!sA) {
        cudaStreamCreateWithFlags(&sA, cudaStreamNonBlocking);
        cudaEventCreateWithFlags(&evFork, cudaEventDisableTiming);
        cudaEventCreateWithFlags(&evA, cudaEventDisableTiming);
        cudaFuncSetAttribute(ff1_mma, cudaFuncAttributeMaxDynamicSharedMemorySize, DYN_SMEM);
        cudaFuncSetAttribute(ff2_mma, cudaFuncAttributeMaxDynamicSharedMemorySize, DYN_SMEM);
    }

    zero_kernel<<<(NTOK * DM) / (256 * 4), 256>>>(out);
    cudaEventRecord(evFork, 0);

    cudaStreamWaitEvent(sA, evFork, 0);
    prep_all<<<XB + 8192, 256, 0, sA>>>(x, w1, w2);
    cudaEventRecord(evA, sA);

    route_kernel<<<NTOK / 4, 128>>>(x, centroids, w_route);

    cudaStreamWaitEvent(0, evA, 0);
    ff1_mma<<<dim3(NTOK / 128, DE / 128, NE), 256, DYN_SMEM>>>(b1);
    ff2_mma<<<dim3(NTOK / 128, DM / 128, NE), 256, DYN_SMEM>>>(b2, out);
}

// round 13
// speedup vs baseline: 1.9334x; 1.9334x over previous
#include <cuda_runtime.h>
#include <cuda_fp16.h>
#include <stdint.h>
#include <math.h>

#define NTOK 8192          // B*S
#define DM 1024
#define DE 512
#define NE 8

// ---------------- scratch (device globals) ----------------
__device__ int   g_count[NE];
__device__ int   g_tok [NE * NTOK];
__device__ float g_gate[NE * NTOK];
__device__ __half g_x16[(size_t)NTOK * DM];
__device__ __half g_h16[(size_t)NE * NTOK * DE];
__device__ __half g_w1t[(size_t)NE * DE * DM];   // [e][n][k] k-major, fp16
__device__ __half g_w2t[(size_t)NE * DM * DE];   // [e][n][k] fp16

// ---------------- helpers ----------------
static __device__ __forceinline__ uint32_t smem_u32(const void* p) {
    uint32_t a;
    asm("{ .reg .u64 t; cvta.to.shared.u64 t, %1; cvt.u32.u64 %0, t; }"
        : "=r"(a) : "l"(p));
    return a;
}

static __device__ __forceinline__ void cpa16(uint32_t dst, const void* src) {
    asm volatile("cp.async.cg.shared.global [%0], [%1], 16;" :: "r"(dst), "l"(src));
}
#define CP_COMMIT() asm volatile("cp.async.commit_group;" ::: "memory")
#define CP_WAIT2()  asm volatile("cp.async.wait_group 2;" ::: "memory")

#define LDMX4(r0, r1, r2, r3, addr)                                          \
    asm volatile("ldmatrix.sync.aligned.m8n8.x4.shared.b16 {%0,%1,%2,%3}, [%4];" \
        : "=r"(r0), "=r"(r1), "=r"(r2), "=r"(r3) : "r"(addr))

#define MMA(ac, a, b)                                                        \
    asm volatile("mma.sync.aligned.m16n8k16.row.col.f32.f16.f16.f32 "        \
        "{%0,%1,%2,%3}, {%4,%5,%6,%7}, {%8,%9}, {%0,%1,%2,%3};"              \
        : "+f"((ac)[0]), "+f"((ac)[1]), "+f"((ac)[2]), "+f"((ac)[3])         \
        : "r"((a)[0]), "r"((a)[1]), "r"((a)[2]), "r"((a)[3]),                \
          "r"((b)[0]), "r"((b)[1]))

// ============================================================
// 0) zero output + counters
// ============================================================
__global__ void zero_kernel(float* __restrict__ out) {
    int idx = blockIdx.x * blockDim.x + threadIdx.x;
    ((float4*)out)[idx] = make_float4(0.f, 0.f, 0.f, 0.f);
    if (blockIdx.x == 0 && threadIdx.x < NE) g_count[threadIdx.x] = 0;
}

// ============================================================
// 1) merged prep: x -> fp16 + w1/w2 transpose to fp16
//    grid: [0,8192) x-convert, [8192,12288) w1, [12288,16384) w2
// ============================================================
#define XB 8192
__global__ void prep_all(const float* __restrict__ x,
                         const float* __restrict__ w1,
                         const float* __restrict__ w2) {
    __shared__ float t[32][33];
    int b = blockIdx.x, tid = threadIdx.x;

    if (b < XB) {
        size_t i = (size_t)b * 256 + tid;   // float4 index
        float4 v = ((const float4*)x)[i];
        unsigned u0 = (unsigned)__half_as_ushort(__float2half_rn(v.x)) |
                      ((unsigned)__half_as_ushort(__float2half_rn(v.y)) << 16);
        unsigned u1 = (unsigned)__half_as_ushort(__float2half_rn(v.z)) |
                      ((unsigned)__half_as_ushort(__float2half_rn(v.w)) << 16);
        ((uint2*)g_x16)[i] = make_uint2(u0, u1);
        return;
    }

    const float* in;
    __half* outp;
    int K, N, nblk;
    if (b < XB + 4096) { b -= XB;        in = w1; outp = g_w1t; K = DM; N = DE; nblk = 16; }
    else               { b -= XB + 4096; in = w2; outp = g_w2t; K = DE; N = DM; nblk = 32; }

    int per_e = nblk * (K / 32);
    int e   = b / per_e;
    int rem = b % per_e;
    int n0  = (rem % nblk) * 32;
    int k0  = (rem / nblk) * 32;
    int tx  = tid & 31, ty = tid >> 5;

    const float* pin = in + (size_t)e * K * N;
#pragma unroll
    for (int i = 0; i < 4; i++)
        t[ty + i * 8][tx] = pin[(size_t)(k0 + ty + i * 8) * N + n0 + tx];
    __syncthreads();
#pragma unroll
    for (int i = 0; i < 4; i++) {
        int nl = ty + i * 8, kl = tx;
        outp[((size_t)e * N + n0 + nl) * K + k0 + kl] = __float2half_rn(t[kl][nl]);
    }
}

// ============================================================
// 2) routing: one warp per token
// ============================================================
__global__ void route_kernel(const float* __restrict__ x,
                             const float* __restrict__ centroids,
                             const float* __restrict__ w_route) {
    int gwarp = (blockIdx.x * blockDim.x + threadIdx.x) >> 5;
    int lane  = threadIdx.x & 31;
    if (gwarp >= NTOK) return;
    int tok = gwarp;

    const float4* xr = (const float4*)(x + (size_t)tok * DM);
    float4 xv[8];
#pragma unroll
    for (int u = 0; u < 8; u++) xv[u] = xr[u * 32 + lane];

    float nx = 0.f;
#pragma unroll
    for (int u = 0; u < 8; u++) {
        float4 v = xv[u];
        nx += v.x * v.x + v.y * v.y + v.z * v.z + v.w * v.w;
    }
#pragma unroll
    for (int off = 16; off; off >>= 1) nx += __shfl_xor_sync(0xffffffffu, nx, off);
    float xn = fmaxf(sqrtf(nx), 1e-12f);

    float logits[NE];
#pragma unroll
    for (int e = 0; e < NE; e++) {
        const float4* cr = (const float4*)(centroids + (size_t)e * DM);
        const float4* wr = (const float4*)(w_route   + (size_t)e * DM);
        float sc = 0.f, scc = 0.f, sr = 0.f;
#pragma unroll
        for (int u = 0; u < 8; u++) {
            float4 c = cr[u * 32 + lane];
            float4 w = wr[u * 32 + lane];
            float4 v = xv[u];
            sc  += v.x * c.x + v.y * c.y + v.z * c.z + v.w * c.w;
            scc += c.x * c.x + c.y * c.y + c.z * c.z + c.w * c.w;
            sr  += v.x * w.x + v.y * w.y + v.z * w.z + v.w * w.w;
        }
#pragma unroll
        for (int off = 16; off; off >>= 1) {
            sc  += __shfl_xor_sync(0xffffffffu, sc,  off);
            scc += __shfl_xor_sync(0xffffffffu, scc, off);
            sr  += __shfl_xor_sync(0xffffffffu, sr,  off);
        }
        float cn = fmaxf(sqrtf(scc), 1e-12f);
        logits[e] = sc / (xn * cn) + sr;
    }

    if (lane == 0) {
        int e1 = 0; float l1 = logits[0];
#pragma unroll
        for (int e = 1; e < NE; e++) if (logits[e] > l1) { l1 = logits[e]; e1 = e; }
        int e2 = -1; float l2 = -INFINITY;
#pragma unroll
        for (int e = 0; e < NE; e++) if (e != e1 && logits[e] > l2) { l2 = logits[e]; e2 = e; }
        float b  = expf(l2 - l1);
        float g1 = 1.f / (1.f + b);
        float g2 = b  / (1.f + b);
        int p1 = atomicAdd(&g_count[e1], 1);
        g_tok [e1 * NTOK + p1] = tok;
        g_gate[e1 * NTOK + p1] = g1;
        int p2 = atomicAdd(&g_count[e2], 1);
        g_tok [e2 * NTOK + p2] = tok;
        g_gate[e2 * NTOK + p2] = g2;
    }
}

// ============================================================
// GEMM geometry: block 128x128, BK=32, 8 warps (2x4), warp 64x32
// pure fp16 A*B, 3-stage ring, R10-proven loop structure
// smem row: 32 fp16 + 8 pad = 80 B; 2 tiles (A, B) per stage
// ============================================================
#define BK 32
#define SROWB 80
#define TILE_B (128 * SROWB)          // 10240 B
#define STAGE_B (2 * TILE_B)          // 20480 B
#define DYN_SMEM (3 * STAGE_B)        // 61440 B, 2 CTA/SM

#define MMA_KSTEP(sb)                                                        \
    do {                                                                     \
        uint32_t ah[4][4], bh[4][2];                                         \
        _Pragma("unroll")                                                    \
        for (int mt = 0; mt < 4; mt++) {                                     \
            uint32_t aa = (sb) + a_off + mt * 16 * SROWB + ks * 32;          \
            LDMX4(ah[mt][0], ah[mt][1], ah[mt][2], ah[mt][3], aa);           \
        }                                                                    \
        _Pragma("unroll")                                                    \
        for (int p = 0; p < 2; p++) {                                        \
            uint32_t ba = (sb) + TILE_B + b_off + p * 16 * SROWB + ks * 32;  \
            uint32_t t0, t1, t2, t3;                                         \
            LDMX4(t0, t1, t2, t3, ba);                                       \
            bh[2 * p][0] = t0; bh[2 * p][1] = t1;                            \
            bh[2 * p + 1][0] = t2; bh[2 * p + 1][1] = t3;                    \
        }                                                                    \
        _Pragma("unroll")                                                    \
        for (int mt = 0; mt < 4; mt++)                                       \
            _Pragma("unroll")                                                \
            for (int nt = 0; nt < 4; nt++) MMA(acc[mt][nt], ah[mt], bh[nt]); \
    } while (0)

// ============================================================
// 3) FF1: h = gelu(gather(x) @ w1[e] + b1[e])
// ============================================================
__global__ __launch_bounds__(256, 2) void ff1_mma(const float* __restrict__ b1) {
    extern __shared__ char dsm[];
    __shared__ int rows_s[128];

    int e   = blockIdx.z;
    int cnt = g_count[e];
    int m0  = blockIdx.x * 128;
    if (m0 >= cnt) return;
    int n0  = blockIdx.y * 128;
    int tid = threadIdx.x, lane = tid & 31, wid = tid >> 5;
    int warpM = wid >> 2, warpN = wid & 3;

    if (tid < 128) {
        int m = m0 + tid;
        rows_s[tid] = (m < cnt) ? g_tok[e * NTOK + m] : 0;
    }
    __syncthreads();

    uint32_t sbase = smem_u32(dsm);

    int arow = lane & 15;
    int akad = (lane >> 4) << 3;
    int brow = ((lane & 16) >> 1) | (lane & 7);
    int bkad = lane & 8;
    uint32_t a_off = (uint32_t)((warpM * 64 + arow) * SROWB + akad * 2);
    uint32_t b_off = (uint32_t)((warpN * 32 + brow) * SROWB + bkad * 2);

    float acc[4][4][4];
#pragma unroll
    for (int mt = 0; mt < 4; mt++)
#pragma unroll
        for (int nt = 0; nt < 4; nt++)
#pragma unroll
            for (int q = 0; q < 4; q++) acc[mt][nt][q] = 0.f;

    const int NC = DM / BK;   // 32

    auto load_stage = [&](int s, int k0) {
        uint32_t sb = sbase + s * STAGE_B;
#pragma unroll
        for (int j = 0; j < 2; j++) {
            int ci  = tid + j * 256;          // 0..511
            int row = ci >> 2, kc = ci & 3;
            uint32_t d0 = sb + row * SROWB + kc * 16;
            size_t ax = (size_t)rows_s[row] * DM + k0 + kc * 8;
            cpa16(d0,          g_x16 + ax);
            size_t bx = ((size_t)e * DE + n0 + row) * DM + k0 + kc * 8;
            cpa16(d0 + TILE_B, g_w1t + bx);
        }
    };

    load_stage(0, 0); CP_COMMIT();
    load_stage(1, BK); CP_COMMIT();

    int sc = 0;
    for (int c = 0; c < NC; c++) {
        if (c + 2 < NC) {
            int sn = sc + 2; if (sn >= 3) sn -= 3;
            load_stage(sn, (c + 2) * BK);
        }
        CP_COMMIT();
        CP_WAIT2();
        __syncthreads();
        uint32_t sb = sbase + sc * STAGE_B;
#pragma unroll
        for (int ks = 0; ks < 2; ks++) { MMA_KSTEP(sb); }
        __syncthreads();
        if (++sc == 3) sc = 0;
    }

    // ---- epilogue: bias + gelu -> fp16 ----
    int r = lane >> 2, cp = (lane & 3) * 2;
#pragma unroll
    for (int mt = 0; mt < 4; mt++)
#pragma unroll
        for (int half = 0; half < 2; half++) {
            int m = m0 + warpM * 64 + mt * 16 + r + half * 8;
            if (m >= cnt) continue;
            size_t base = ((size_t)e * NTOK + m) * DE;
#pragma unroll
            for (int nt = 0; nt < 4; nt++) {
                int nn = n0 + warpN * 32 + nt * 8 + cp;
                float v0 = acc[mt][nt][half * 2 + 0] + b1[e * DE + nn];
                float v1 = acc[mt][nt][half * 2 + 1] + b1[e * DE + nn + 1];
                v0 = 0.5f * v0 * (1.0f + erff(v0 * 0.7071067811865476f));
                v1 = 0.5f * v1 * (1.0f + erff(v1 * 0.7071067811865476f));
                unsigned u = (unsigned)__half_as_ushort(__float2half_rn(v0)) |
                             ((unsigned)__half_as_ushort(__float2half_rn(v1)) << 16);
                *(unsigned*)((__half*)g_h16 + base + nn) = u;
            }
        }
}

// ============================================================
// 4) FF2: out[tok] += gate * (h @ w2[e] + b2[e])
// ============================================================
__global__ __launch_bounds__(256, 2) void ff2_mma(const float* __restrict__ b2,
                                                  float* __restrict__ out) {
    extern __shared__ char dsm[];

    int e   = blockIdx.z;
    int cnt = g_count[e];
    int m0  = blockIdx.x * 128;
    if (m0 >= cnt) return;
    int n0  = blockIdx.y * 128;
    int tid = threadIdx.x, lane = tid & 31, wid = tid >> 5;
    int warpM = wid >> 2, warpN = wid & 3;

    uint32_t sbase = smem_u32(dsm);

    int arow = lane & 15;
    int akad = (lane >> 4) << 3;
    int brow = ((lane & 16) >> 1) | (lane & 7);
    int bkad = lane & 8;
    uint32_t a_off = (uint32_t)((warpM * 64 + arow) * SROWB + akad * 2);
    uint32_t b_off = (uint32_t)((warpN * 32 + brow) * SROWB + bkad * 2);

    float acc[4][4][4];
#pragma unroll
    for (int mt = 0; mt < 4; mt++)
#pragma unroll
        for (int nt = 0; nt < 4; nt++)
#pragma unroll
            for (int q = 0; q < 4; q++) acc[mt][nt][q] = 0.f;

    const int NC = DE / BK;   // 16

    auto load_stage = [&](int s, int k0) {
        uint32_t sb = sbase + s * STAGE_B;
#pragma unroll
        for (int j = 0; j < 2; j++) {
            int ci  = tid + j * 256;
            int row = ci >> 2, kc = ci & 3;
            uint32_t d0 = sb + row * SROWB + kc * 16;
            size_t ax = ((size_t)e * NTOK + m0 + row) * DE + k0 + kc * 8;
            cpa16(d0,          g_h16 + ax);
            size_t bx = ((size_t)e * DM + n0 + row) * DE + k0 + kc * 8;
            cpa16(d0 + TILE_B, g_w2t + bx);
        }
    };

    load_stage(0, 0); CP_COMMIT();
    load_stage(1, BK); CP_COMMIT();

    int sc = 0;
    for (int c = 0; c < NC; c++) {
        if (c + 2 < NC) {
            int sn = sc + 2; if (sn >= 3) sn -= 3;
            load_stage(sn, (c + 2) * BK);
        }
        CP_COMMIT();
        CP_WAIT2();
        __syncthreads();
        uint32_t sb = sbase + sc * STAGE_B;
#pragma unroll
        for (int ks = 0; ks < 2; ks++) { MMA_KSTEP(sb); }
        __syncthreads();
        if (++sc == 3) sc = 0;
    }

    // ---- epilogue: gate * (acc + b2) -> atomic add into out ----
    int r = lane >> 2, cp = (lane & 3) * 2;
#pragma unroll
    for (int mt = 0; mt < 4; mt++)
#pragma unroll
        for (int half = 0; half < 2; half++) {
            int m = m0 + warpM * 64 + mt * 16 + r + half * 8;
            if (m >= cnt) continue;
            int   tok  = g_tok [e * NTOK + m];
            float gate = g_gate[e * NTOK + m];
            float* orow = out + (size_t)tok * DM;
#pragma unroll
            for (int nt = 0; nt < 4; nt++) {
                int nn = n0 + warpN * 32 + nt * 8 + cp;
                float v0 = gate * (acc[mt][nt][half * 2 + 0] + b2[e * DM + nn]);
                float v1 = gate * (acc[mt][nt][half * 2 + 1] + b2[e * DM + nn + 1]);
                atomicAdd(&orow[nn],     v0);
                atomicAdd(&orow[nn + 1], v1);
            }
        }
}

// ============================================================
// launcher: zero, prep_all(side stream), route, ff1, ff2
// ============================================================
extern "C" void kernel_launch(void* const* d_in, const int* in_sizes, int n_in,
                              void* d_out, int out_size) {
    const float* x         = (const float*)d_in[0];
    const float* w1        = (const float*)d_in[1];
    const float* b1        = (const float*)d_in[2];
    const float* w2        = (const float*)d_in[3];
    const float* b2        = (const float*)d_in[4];
    const float* centroids = (const float*)d_in[5];
    const float* w_route   = (const float*)d_in[6];
    float* out = (float*)d_out;

    static cudaStream_t sA = nullptr;
    static cudaEvent_t evFork, evA;
    if (!sA) {
        cudaStreamCreateWithFlags(&sA, cudaStreamNonBlocking);
        cudaEventCreateWithFlags(&evFork, cudaEventDisableTiming);
        cudaEventCreateWithFlags(&evA, cudaEventDisableTiming);
        cudaFuncSetAttribute(ff1_mma, cudaFuncAttributeMaxDynamicSharedMemorySize, DYN_SMEM);
        cudaFuncSetAttribute(ff2_mma, cudaFuncAttributeMaxDynamicSharedMemorySize, DYN_SMEM);
    }

    zero_kernel<<<(NTOK * DM) / (256 * 4), 256>>>(out);
    cudaEventRecord(evFork, 0);

    cudaStreamWaitEvent(sA, evFork, 0);
    prep_all<<<XB + 8192, 256, 0, sA>>>(x, w1, w2);
    cudaEventRecord(evA, sA);

    route_kernel<<<NTOK / 4, 128>>>(x, centroids, w_route);

    cudaStreamWaitEvent(0, evA, 0);
    ff1_mma<<<dim3(NTOK / 128, DE / 128, NE), 256, DYN_SMEM>>>(b1);
    ff2_mma<<<dim3(NTOK / 128, DM / 128, NE), 256, DYN_SMEM>>>(b2, out);
}

// round 14
// speedup vs baseline: 1.9976x; 1.0332x over previous
#include <cuda_runtime.h>
#include <cuda_fp16.h>
#include <stdint.h>
#include <math.h>

#define NTOK 8192          // B*S
#define DM 1024
#define DE 512
#define NE 8

// ---------------- scratch (device globals) ----------------
__device__ int   g_count[NE];
__device__ int   g_tok [NE * NTOK];
__device__ float g_gate[NE * NTOK];
__device__ int   g_inv [2 * NTOK];                 // token -> 2 expert-slot locs
__device__ __half g_x16[(size_t)NTOK * DM];
__device__ __half g_h16[(size_t)NE * NTOK * DE];
__device__ __half g_w1t[(size_t)NE * DE * DM];     // [e][n][k] k-major fp16
__device__ __half g_w2t[(size_t)NE * DM * DE];     // [e][n][k] fp16
__device__ float g_eo [(size_t)NE * NTOK * DM];    // expert outputs (incl. b2)

// ---------------- helpers ----------------
static __device__ __forceinline__ uint32_t smem_u32(const void* p) {
    uint32_t a;
    asm("{ .reg .u64 t; cvta.to.shared.u64 t, %1; cvt.u32.u64 %0, t; }"
        : "=r"(a) : "l"(p));
    return a;
}

static __device__ __forceinline__ void cpa16(uint32_t dst, const void* src) {
    asm volatile("cp.async.cg.shared.global [%0], [%1], 16;" :: "r"(dst), "l"(src));
}
#define CP_COMMIT() asm volatile("cp.async.commit_group;" ::: "memory")
#define CP_WAIT2()  asm volatile("cp.async.wait_group 2;" ::: "memory")

#define LDMX4(r0, r1, r2, r3, addr)                                          \
    asm volatile("ldmatrix.sync.aligned.m8n8.x4.shared.b16 {%0,%1,%2,%3}, [%4];" \
        : "=r"(r0), "=r"(r1), "=r"(r2), "=r"(r3) : "r"(addr))

#define MMA(ac, a, b)                                                        \
    asm volatile("mma.sync.aligned.m16n8k16.row.col.f32.f16.f16.f32 "        \
        "{%0,%1,%2,%3}, {%4,%5,%6,%7}, {%8,%9}, {%0,%1,%2,%3};"              \
        : "+f"((ac)[0]), "+f"((ac)[1]), "+f"((ac)[2]), "+f"((ac)[3])         \
        : "r"((a)[0]), "r"((a)[1]), "r"((a)[2]), "r"((a)[3]),                \
          "r"((b)[0]), "r"((b)[1]))

// ============================================================
// 0) zero counters only (out is fully overwritten by combine)
// ============================================================
__global__ void zero_ctr_kernel() {
    if (threadIdx.x < NE) g_count[threadIdx.x] = 0;
}

// ============================================================
// 1) merged prep: x -> fp16 + w1/w2 transpose to fp16
// ============================================================
#define XB 8192
__global__ void prep_all(const float* __restrict__ x,
                         const float* __restrict__ w1,
                         const float* __restrict__ w2) {
    __shared__ float t[32][33];
    int b = blockIdx.x, tid = threadIdx.x;

    if (b < XB) {
        size_t i = (size_t)b * 256 + tid;   // float4 index
        float4 v = ((const float4*)x)[i];
        unsigned u0 = (unsigned)__half_as_ushort(__float2half_rn(v.x)) |
                      ((unsigned)__half_as_ushort(__float2half_rn(v.y)) << 16);
        unsigned u1 = (unsigned)__half_as_ushort(__float2half_rn(v.z)) |
                      ((unsigned)__half_as_ushort(__float2half_rn(v.w)) << 16);
        ((uint2*)g_x16)[i] = make_uint2(u0, u1);
        return;
    }

    const float* in;
    __half* outp;
    int K, N, nblk;
    if (b < XB + 4096) { b -= XB;        in = w1; outp = g_w1t; K = DM; N = DE; nblk = 16; }
    else               { b -= XB + 4096; in = w2; outp = g_w2t; K = DE; N = DM; nblk = 32; }

    int per_e = nblk * (K / 32);
    int e   = b / per_e;
    int rem = b % per_e;
    int n0  = (rem % nblk) * 32;
    int k0  = (rem / nblk) * 32;
    int tx  = tid & 31, ty = tid >> 5;

    const float* pin = in + (size_t)e * K * N;
#pragma unroll
    for (int i = 0; i < 4; i++)
        t[ty + i * 8][tx] = pin[(size_t)(k0 + ty + i * 8) * N + n0 + tx];
    __syncthreads();
#pragma unroll
    for (int i = 0; i < 4; i++) {
        int nl = ty + i * 8, kl = tx;
        outp[((size_t)e * N + n0 + nl) * K + k0 + kl] = __float2half_rn(t[kl][nl]);
    }
}

// ============================================================
// 2) routing: one warp per token (+ inverse map)
// ============================================================
__global__ void route_kernel(const float* __restrict__ x,
                             const float* __restrict__ centroids,
                             const float* __restrict__ w_route) {
    int gwarp = (blockIdx.x * blockDim.x + threadIdx.x) >> 5;
    int lane  = threadIdx.x & 31;
    if (gwarp >= NTOK) return;
    int tok = gwarp;

    const float4* xr = (const float4*)(x + (size_t)tok * DM);
    float4 xv[8];
#pragma unroll
    for (int u = 0; u < 8; u++) xv[u] = xr[u * 32 + lane];

    float nx = 0.f;
#pragma unroll
    for (int u = 0; u < 8; u++) {
        float4 v = xv[u];
        nx += v.x * v.x + v.y * v.y + v.z * v.z + v.w * v.w;
    }
#pragma unroll
    for (int off = 16; off; off >>= 1) nx += __shfl_xor_sync(0xffffffffu, nx, off);
    float xn = fmaxf(sqrtf(nx), 1e-12f);

    float logits[NE];
#pragma unroll
    for (int e = 0; e < NE; e++) {
        const float4* cr = (const float4*)(centroids + (size_t)e * DM);
        const float4* wr = (const float4*)(w_route   + (size_t)e * DM);
        float sc = 0.f, scc = 0.f, sr = 0.f;
#pragma unroll
        for (int u = 0; u < 8; u++) {
            float4 c = cr[u * 32 + lane];
            float4 w = wr[u * 32 + lane];
            float4 v = xv[u];
            sc  += v.x * c.x + v.y * c.y + v.z * c.z + v.w * c.w;
            scc += c.x * c.x + c.y * c.y + c.z * c.z + c.w * c.w;
            sr  += v.x * w.x + v.y * w.y + v.z * w.z + v.w * w.w;
        }
#pragma unroll
        for (int off = 16; off; off >>= 1) {
            sc  += __shfl_xor_sync(0xffffffffu, sc,  off);
            scc += __shfl_xor_sync(0xffffffffu, scc, off);
            sr  += __shfl_xor_sync(0xffffffffu, sr,  off);
        }
        float cn = fmaxf(sqrtf(scc), 1e-12f);
        logits[e] = sc / (xn * cn) + sr;
    }

    if (lane == 0) {
        int e1 = 0; float l1 = logits[0];
#pragma unroll
        for (int e = 1; e < NE; e++) if (logits[e] > l1) { l1 = logits[e]; e1 = e; }
        int e2 = -1; float l2 = -INFINITY;
#pragma unroll
        for (int e = 0; e < NE; e++) if (e != e1 && logits[e] > l2) { l2 = logits[e]; e2 = e; }
        float b  = expf(l2 - l1);
        float g1 = 1.f / (1.f + b);
        float g2 = b  / (1.f + b);
        int p1 = atomicAdd(&g_count[e1], 1);
        g_tok [e1 * NTOK + p1] = tok;
        g_gate[e1 * NTOK + p1] = g1;
        int p2 = atomicAdd(&g_count[e2], 1);
        g_tok [e2 * NTOK + p2] = tok;
        g_gate[e2 * NTOK + p2] = g2;
        g_inv[2 * tok]     = e1 * NTOK + p1;
        g_inv[2 * tok + 1] = e2 * NTOK + p2;
    }
}

// ============================================================
// GEMM geometry: block 128x128, BK=32, 8 warps (2x4), warp 64x32
// pure fp16 A*B; 4-stage ring, ONE __syncthreads per chunk
// ============================================================
#define BK 32
#define SROWB 80
#define TILE_B (128 * SROWB)          // 10240 B
#define STAGE_B (2 * TILE_B)          // 20480 B
#define DYN_SMEM (4 * STAGE_B)        // 81920 B, 2 CTA/SM

#define MMA_KSTEP(sb)                                                        \
    do {                                                                     \
        uint32_t ah[4][4], bh[4][2];                                         \
        _Pragma("unroll")                                                    \
        for (int mt = 0; mt < 4; mt++) {                                     \
            uint32_t aa = (sb) + a_off + mt * 16 * SROWB + ks * 32;          \
            LDMX4(ah[mt][0], ah[mt][1], ah[mt][2], ah[mt][3], aa);           \
        }                                                                    \
        _Pragma("unroll")                                                    \
        for (int p = 0; p < 2; p++) {                                        \
            uint32_t ba = (sb) + TILE_B + b_off + p * 16 * SROWB + ks * 32;  \
            uint32_t t0, t1, t2, t3;                                         \
            LDMX4(t0, t1, t2, t3, ba);                                       \
            bh[2 * p][0] = t0; bh[2 * p][1] = t1;                            \
            bh[2 * p + 1][0] = t2; bh[2 * p + 1][1] = t3;                    \
        }                                                                    \
        _Pragma("unroll")                                                    \
        for (int mt = 0; mt < 4; mt++)                                       \
            _Pragma("unroll")                                                \
            for (int nt = 0; nt < 4; nt++) MMA(acc[mt][nt], ah[mt], bh[nt]); \
    } while (0)

// ============================================================
// 3) FF1: h = gelu(gather(x) @ w1[e] + b1[e])
// ============================================================
__global__ __launch_bounds__(256, 2) void ff1_mma(const float* __restrict__ b1) {
    extern __shared__ char dsm[];
    __shared__ int rows_s[128];

    int e   = blockIdx.z;
    int cnt = g_count[e];
    int m0  = blockIdx.x * 128;
    if (m0 >= cnt) return;
    int n0  = blockIdx.y * 128;
    int tid = threadIdx.x, lane = tid & 31, wid = tid >> 5;
    int warpM = wid >> 2, warpN = wid & 3;

    if (tid < 128) {
        int m = m0 + tid;
        rows_s[tid] = (m < cnt) ? g_tok[e * NTOK + m] : 0;
    }
    __syncthreads();

    uint32_t sbase = smem_u32(dsm);

    int arow = lane & 15;
    int akad = (lane >> 4) << 3;
    int brow = ((lane & 16) >> 1) | (lane & 7);
    int bkad = lane & 8;
    uint32_t a_off = (uint32_t)((warpM * 64 + arow) * SROWB + akad * 2);
    uint32_t b_off = (uint32_t)((warpN * 32 + brow) * SROWB + bkad * 2);

    float acc[4][4][4];
#pragma unroll
    for (int mt = 0; mt < 4; mt++)
#pragma unroll
        for (int nt = 0; nt < 4; nt++)
#pragma unroll
            for (int q = 0; q < 4; q++) acc[mt][nt][q] = 0.f;

    const int NC = DM / BK;   // 32

    auto load_stage = [&](int s, int k0) {
        uint32_t sb = sbase + s * STAGE_B;
#pragma unroll
        for (int j = 0; j < 2; j++) {
            int ci  = tid + j * 256;          // 0..511
            int row = ci >> 2, kc = ci & 3;
            uint32_t d0 = sb + row * SROWB + kc * 16;
            size_t ax = (size_t)rows_s[row] * DM + k0 + kc * 8;
            cpa16(d0,          g_x16 + ax);
            size_t bx = ((size_t)e * DE + n0 + row) * DM + k0 + kc * 8;
            cpa16(d0 + TILE_B, g_w1t + bx);
        }
    };

    load_stage(0, 0); CP_COMMIT();
    load_stage(1, BK); CP_COMMIT();

    for (int c = 0; c < NC; c++) {
        if (c + 2 < NC) load_stage((c + 2) & 3, (c + 2) * BK);
        CP_COMMIT();
        CP_WAIT2();
        __syncthreads();
        uint32_t sb = sbase + (c & 3) * STAGE_B;
#pragma unroll
        for (int ks = 0; ks < 2; ks++) { MMA_KSTEP(sb); }
    }

    // ---- epilogue: bias + gelu -> fp16 ----
    int r = lane >> 2, cp = (lane & 3) * 2;
#pragma unroll
    for (int mt = 0; mt < 4; mt++)
#pragma unroll
        for (int half = 0; half < 2; half++) {
            int m = m0 + warpM * 64 + mt * 16 + r + half * 8;
            if (m >= cnt) continue;
            size_t base = ((size_t)e * NTOK + m) * DE;
#pragma unroll
            for (int nt = 0; nt < 4; nt++) {
                int nn = n0 + warpN * 32 + nt * 8 + cp;
                float v0 = acc[mt][nt][half * 2 + 0] + b1[e * DE + nn];
                float v1 = acc[mt][nt][half * 2 + 1] + b1[e * DE + nn + 1];
                v0 = 0.5f * v0 * (1.0f + erff(v0 * 0.7071067811865476f));
                v1 = 0.5f * v1 * (1.0f + erff(v1 * 0.7071067811865476f));
                unsigned u = (unsigned)__half_as_ushort(__float2half_rn(v0)) |
                             ((unsigned)__half_as_ushort(__float2half_rn(v1)) << 16);
                *(unsigned*)((__half*)g_h16 + base + nn) = u;
            }
        }
}

// ============================================================
// 4) FF2: eo[e][slot] = h @ w2[e] + b2[e]   (plain stores, no atomics)
// ============================================================
__global__ __launch_bounds__(256, 2) void ff2_mma(const float* __restrict__ b2) {
    extern __shared__ char dsm[];

    int e   = blockIdx.z;
    int cnt = g_count[e];
    int m0  = blockIdx.x * 128;
    if (m0 >= cnt) return;
    int n0  = blockIdx.y * 128;
    int tid = threadIdx.x, lane = tid & 31, wid = tid >> 5;
    int warpM = wid >> 2, warpN = wid & 3;

    uint32_t sbase = smem_u32(dsm);

    int arow = lane & 15;
    int akad = (lane >> 4) << 3;
    int brow = ((lane & 16) >> 1) | (lane & 7);
    int bkad = lane & 8;
    uint32_t a_off = (uint32_t)((warpM * 64 + arow) * SROWB + akad * 2);
    uint32_t b_off = (uint32_t)((warpN * 32 + brow) * SROWB + bkad * 2);

    float acc[4][4][4];
#pragma unroll
    for (int mt = 0; mt < 4; mt++)
#pragma unroll
        for (int nt = 0; nt < 4; nt++)
#pragma unroll
            for (int q = 0; q < 4; q++) acc[mt][nt][q] = 0.f;

    const int NC = DE / BK;   // 16

    auto load_stage = [&](int s, int k0) {
        uint32_t sb = sbase + s * STAGE_B;
#pragma unroll
        for (int j = 0; j < 2; j++) {
            int ci  = tid + j * 256;
            int row = ci >> 2, kc = ci & 3;
            uint32_t d0 = sb + row * SROWB + kc * 16;
            size_t ax = ((size_t)e * NTOK + m0 + row) * DE + k0 + kc * 8;
            cpa16(d0,          g_h16 + ax);
            size_t bx = ((size_t)e * DM + n0 + row) * DE + k0 + kc * 8;
            cpa16(d0 + TILE_B, g_w2t + bx);
        }
    };

    load_stage(0, 0); CP_COMMIT();
    load_stage(1, BK); CP_COMMIT();

    for (int c = 0; c < NC; c++) {
        if (c + 2 < NC) load_stage((c + 2) & 3, (c + 2) * BK);
        CP_COMMIT();
        CP_WAIT2();
        __syncthreads();
        uint32_t sb = sbase + (c & 3) * STAGE_B;
#pragma unroll
        for (int ks = 0; ks < 2; ks++) { MMA_KSTEP(sb); }
    }

    // ---- epilogue: eo = acc + b2 (plain stores) ----
    int r = lane >> 2, cp = (lane & 3) * 2;
#pragma unroll
    for (int mt = 0; mt < 4; mt++)
#pragma unroll
        for (int half = 0; half < 2; half++) {
            int m = m0 + warpM * 64 + mt * 16 + r + half * 8;
            if (m >= cnt) continue;
            float* erow = g_eo + ((size_t)e * NTOK + m) * DM;
#pragma unroll
            for (int nt = 0; nt < 4; nt++) {
                int nn = n0 + warpN * 32 + nt * 8 + cp;
                float v0 = acc[mt][nt][half * 2 + 0] + b2[e * DM + nn];
                float v1 = acc[mt][nt][half * 2 + 1] + b2[e * DM + nn + 1];
                *(float2*)(erow + nn) = make_float2(v0, v1);
            }
        }
}

// ============================================================
// 5) combine: out[tok] = g1*eo[loc1] + g2*eo[loc2]   (one warp/token)
// ============================================================
__global__ __launch_bounds__(256) void combine_kernel(float* __restrict__ out) {
    int tok  = (blockIdx.x * blockDim.x + threadIdx.x) >> 5;
    int lane = threadIdx.x & 31;
    if (tok >= NTOK) return;
    int loc1 = g_inv[2 * tok], loc2 = g_inv[2 * tok + 1];
    float g1 = g_gate[loc1], g2 = g_gate[loc2];
    const float4* e1 = (const float4*)(g_eo + (size_t)loc1 * DM);
    const float4* e2 = (const float4*)(g_eo + (size_t)loc2 * DM);
    float4* o = (float4*)(out + (size_t)tok * DM);
#pragma unroll
    for (int i = 0; i < 8; i++) {
        float4 a = e1[lane + i * 32];
        float4 b = e2[lane + i * 32];
        o[lane + i * 32] = make_float4(g1 * a.x + g2 * b.x, g1 * a.y + g2 * b.y,
                                       g1 * a.z + g2 * b.z, g1 * a.w + g2 * b.w);
    }
}

// ============================================================
// launcher: prep(side, t=0) || [zero_ctr, route] ; join ; ff1, ff2, combine
// ============================================================
extern "C" void kernel_launch(void* const* d_in, const int* in_sizes, int n_in,
                              void* d_out, int out_size) {
    const float* x         = (const float*)d_in[0];
    const float* w1        = (const float*)d_in[1];
    const float* b1        = (const float*)d_in[2];
    const float* w2        = (const float*)d_in[3];
    const float* b2        = (const float*)d_in[4];
    const float* centroids = (const float*)d_in[5];
    const float* w_route   = (const float*)d_in[6];
    float* out = (float*)d_out;

    static cudaStream_t sA = nullptr;
    static cudaEvent_t evFork, evA;
    if (!sA) {
        cudaStreamCreateWithFlags(&sA, cudaStreamNonBlocking);
        cudaEventCreateWithFlags(&evFork, cudaEventDisableTiming);
        cudaEventCreateWithFlags(&evA, cudaEventDisableTiming);
        cudaFuncSetAttribute(ff1_mma, cudaFuncAttributeMaxDynamicSharedMemorySize, DYN_SMEM);
        cudaFuncSetAttribute(ff2_mma, cudaFuncAttributeMaxDynamicSharedMemorySize, DYN_SMEM);
    }

    cudaEventRecord(evFork, 0);
    cudaStreamWaitEvent(sA, evFork, 0);
    prep_all<<<XB + 8192, 256, 0, sA>>>(x, w1, w2);
    cudaEventRecord(evA, sA);

    zero_ctr_kernel<<<1, 32>>>();
    route_kernel<<<NTOK / 4, 128>>>(x, centroids, w_route);

    cudaStreamWaitEvent(0, evA, 0);
    ff1_mma<<<dim3(NTOK / 128, DE / 128, NE), 256, DYN_SMEM>>>(b1);
    ff2_mma<<<dim3(NTOK / 128, DM / 128, NE), 256, DYN_SMEM>>>(b2);
    combine_kernel<<<NTOK / 8, 256>>>(out);
}

// round 15
// speedup vs baseline: 2.0992x; 1.0508x over previous
#include <cuda_runtime.h>
#include <cuda_fp16.h>
#include <stdint.h>
#include <math.h>

#define NTOK 8192          // B*S
#define DM 1024
#define DE 512
#define NE 8

// ---------------- scratch (device globals) ----------------
__device__ int   g_count[NE];
__device__ int   g_tok [NE * NTOK];
__device__ float g_gate[NE * NTOK];
__device__ float g_cinv[NE];                       // 1/||centroid_e||
__device__ int   g_inv [2 * NTOK];                 // token -> 2 expert-slot locs
__device__ __half g_x16[(size_t)NTOK * DM];
__device__ __half g_h16[(size_t)NE * NTOK * DE];
__device__ __half g_w1t[(size_t)NE * DE * DM];     // [e][n][k] k-major fp16
__device__ __half g_w2t[(size_t)NE * DM * DE];     // [e][n][k] fp16
__device__ float g_eo [(size_t)NE * NTOK * DM];    // expert outputs (incl. b2)

// ---------------- helpers ----------------
static __device__ __forceinline__ uint32_t smem_u32(const void* p) {
    uint32_t a;
    asm("{ .reg .u64 t; cvta.to.shared.u64 t, %1; cvt.u32.u64 %0, t; }"
        : "=r"(a) : "l"(p));
    return a;
}

static __device__ __forceinline__ void cpa16(uint32_t dst, const void* src) {
    asm volatile("cp.async.cg.shared.global [%0], [%1], 16;" :: "r"(dst), "l"(src));
}
#define CP_COMMIT() asm volatile("cp.async.commit_group;" ::: "memory")
#define CP_WAIT2()  asm volatile("cp.async.wait_group 2;" ::: "memory")

#define LDMX4(r0, r1, r2, r3, addr)                                          \
    asm volatile("ldmatrix.sync.aligned.m8n8.x4.shared.b16 {%0,%1,%2,%3}, [%4];" \
        : "=r"(r0), "=r"(r1), "=r"(r2), "=r"(r3) : "r"(addr))

#define MMA(ac, a, b)                                                        \
    asm volatile("mma.sync.aligned.m16n8k16.row.col.f32.f16.f16.f32 "        \
        "{%0,%1,%2,%3}, {%4,%5,%6,%7}, {%8,%9}, {%0,%1,%2,%3};"              \
        : "+f"((ac)[0]), "+f"((ac)[1]), "+f"((ac)[2]), "+f"((ac)[3])         \
        : "r"((a)[0]), "r"((a)[1]), "r"((a)[2]), "r"((a)[3]),                \
          "r"((b)[0]), "r"((b)[1]))

// ============================================================
// 0) init: zero counters + precompute centroid inverse norms
//    one block, 256 threads; warp e reduces centroid e
// ============================================================
__global__ void init_kernel(const float* __restrict__ centroids) {
    int wid = threadIdx.x >> 5, lane = threadIdx.x & 31;
    if (threadIdx.x < NE) g_count[threadIdx.x] = 0;
    const float4* cr = (const float4*)(centroids + (size_t)wid * DM);
    float s = 0.f;
#pragma unroll
    for (int u = 0; u < 8; u++) {
        float4 c = cr[u * 32 + lane];
        s += c.x * c.x + c.y * c.y + c.z * c.z + c.w * c.w;
    }
#pragma unroll
    for (int off = 16; off; off >>= 1) s += __shfl_xor_sync(0xffffffffu, s, off);
    if (lane == 0) g_cinv[wid] = 1.0f / fmaxf(sqrtf(s), 1e-12f);
}

// ============================================================
// 1) merged prep: x -> fp16 + w1/w2 transpose to fp16
// ============================================================
#define XB 8192
__global__ void prep_all(const float* __restrict__ x,
                         const float* __restrict__ w1,
                         const float* __restrict__ w2) {
    __shared__ float t[32][33];
    int b = blockIdx.x, tid = threadIdx.x;

    if (b < XB) {
        size_t i = (size_t)b * 256 + tid;   // float4 index
        float4 v = ((const float4*)x)[i];
        unsigned u0 = (unsigned)__half_as_ushort(__float2half_rn(v.x)) |
                      ((unsigned)__half_as_ushort(__float2half_rn(v.y)) << 16);
        unsigned u1 = (unsigned)__half_as_ushort(__float2half_rn(v.z)) |
                      ((unsigned)__half_as_ushort(__float2half_rn(v.w)) << 16);
        ((uint2*)g_x16)[i] = make_uint2(u0, u1);
        return;
    }

    const float* in;
    __half* outp;
    int K, N, nblk;
    if (b < XB + 4096) { b -= XB;        in = w1; outp = g_w1t; K = DM; N = DE; nblk = 16; }
    else               { b -= XB + 4096; in = w2; outp = g_w2t; K = DE; N = DM; nblk = 32; }

    int per_e = nblk * (K / 32);
    int e   = b / per_e;
    int rem = b % per_e;
    int n0  = (rem % nblk) * 32;
    int k0  = (rem / nblk) * 32;
    int tx  = tid & 31, ty = tid >> 5;

    const float* pin = in + (size_t)e * K * N;
#pragma unroll
    for (int i = 0; i < 4; i++)
        t[ty + i * 8][tx] = pin[(size_t)(k0 + ty + i * 8) * N + n0 + tx];
    __syncthreads();
#pragma unroll
    for (int i = 0; i < 4; i++) {
        int nl = ty + i * 8, kl = tx;
        outp[((size_t)e * N + n0 + nl) * K + k0 + kl] = __float2half_rn(t[kl][nl]);
    }
}

// ============================================================
// 2) routing: one warp per token; centroid norms precomputed
// ============================================================
__global__ void route_kernel(const float* __restrict__ x,
                             const float* __restrict__ centroids,
                             const float* __restrict__ w_route) {
    int gwarp = (blockIdx.x * blockDim.x + threadIdx.x) >> 5;
    int lane  = threadIdx.x & 31;
    if (gwarp >= NTOK) return;
    int tok = gwarp;

    const float4* xr = (const float4*)(x + (size_t)tok * DM);
    float4 xv[8];
#pragma unroll
    for (int u = 0; u < 8; u++) xv[u] = xr[u * 32 + lane];

    float nx = 0.f;
#pragma unroll
    for (int u = 0; u < 8; u++) {
        float4 v = xv[u];
        nx += v.x * v.x + v.y * v.y + v.z * v.z + v.w * v.w;
    }
#pragma unroll
    for (int off = 16; off; off >>= 1) nx += __shfl_xor_sync(0xffffffffu, nx, off);
    float xn = fmaxf(sqrtf(nx), 1e-12f);

    float dcos[NE], drt[NE];
#pragma unroll
    for (int e = 0; e < NE; e++) {
        const float4* cr = (const float4*)(centroids + (size_t)e * DM);
        const float4* wr = (const float4*)(w_route   + (size_t)e * DM);
        float sc = 0.f, sr = 0.f;
#pragma unroll
        for (int u = 0; u < 8; u++) {
            float4 c = cr[u * 32 + lane];
            float4 w = wr[u * 32 + lane];
            float4 v = xv[u];
            sc += v.x * c.x + v.y * c.y + v.z * c.z + v.w * c.w;
            sr += v.x * w.x + v.y * w.y + v.z * w.z + v.w * w.w;
        }
#pragma unroll
        for (int off = 16; off; off >>= 1) {
            sc += __shfl_xor_sync(0xffffffffu, sc, off);
            sr += __shfl_xor_sync(0xffffffffu, sr, off);
        }
        dcos[e] = sc; drt[e] = sr;
    }

    if (lane == 0) {
        float logits[NE];
#pragma unroll
        for (int e = 0; e < NE; e++)
            logits[e] = dcos[e] * g_cinv[e] / xn + drt[e];
        int e1 = 0; float l1 = logits[0];
#pragma unroll
        for (int e = 1; e < NE; e++) if (logits[e] > l1) { l1 = logits[e]; e1 = e; }
        int e2 = -1; float l2 = -INFINITY;
#pragma unroll
        for (int e = 0; e < NE; e++) if (e != e1 && logits[e] > l2) { l2 = logits[e]; e2 = e; }
        float b  = expf(l2 - l1);
        float g1 = 1.f / (1.f + b);
        float g2 = b  / (1.f + b);
        int p1 = atomicAdd(&g_count[e1], 1);
        g_tok [e1 * NTOK + p1] = tok;
        g_gate[e1 * NTOK + p1] = g1;
        int p2 = atomicAdd(&g_count[e2], 1);
        g_tok [e2 * NTOK + p2] = tok;
        g_gate[e2 * NTOK + p2] = g2;
        g_inv[2 * tok]     = e1 * NTOK + p1;
        g_inv[2 * tok + 1] = e2 * NTOK + p2;
    }
}

// ============================================================
// GEMM geometry: block 128x128, BK=32, 4 warps (2x2), warp 64x64
// pure fp16 A*B; 4-stage ring; 128 threads, 2 CTA/SM
// ============================================================
#define BK 32
#define SROWB 80
#define TILE_B (128 * SROWB)          // 10240 B
#define STAGE_B (2 * TILE_B)          // 20480 B
#define DYN_SMEM (4 * STAGE_B)        // 81920 B

#define MMA_KSTEP(sb)                                                        \
    do {                                                                     \
        uint32_t ah[4][4], bh[8][2];                                         \
        _Pragma("unroll")                                                    \
        for (int mt = 0; mt < 4; mt++) {                                     \
            uint32_t aa = (sb) + a_off + mt * 16 * SROWB + ks * 32;          \
            LDMX4(ah[mt][0], ah[mt][1], ah[mt][2], ah[mt][3], aa);           \
        }                                                                    \
        _Pragma("unroll")                                                    \
        for (int p = 0; p < 4; p++) {                                        \
            uint32_t ba = (sb) + TILE_B + b_off + p * 16 * SROWB + ks * 32;  \
            uint32_t t0, t1, t2, t3;                                         \
            LDMX4(t0, t1, t2, t3, ba);                                       \
            bh[2 * p][0] = t0; bh[2 * p][1] = t1;                            \
            bh[2 * p + 1][0] = t2; bh[2 * p + 1][1] = t3;                    \
        }                                                                    \
        _Pragma("unroll")                                                    \
        for (int mt = 0; mt < 4; mt++)                                       \
            _Pragma("unroll")                                                \
            for (int nt = 0; nt < 8; nt++) MMA(acc[mt][nt], ah[mt], bh[nt]); \
    } while (0)

// ============================================================
// 3) FF1: h = gelu(gather(x) @ w1[e] + b1[e])
// ============================================================
__global__ __launch_bounds__(128, 2) void ff1_mma(const float* __restrict__ b1) {
    extern __shared__ char dsm[];
    __shared__ int rows_s[128];

    int e   = blockIdx.z;
    int cnt = g_count[e];
    int m0  = blockIdx.x * 128;
    if (m0 >= cnt) return;
    int n0  = blockIdx.y * 128;
    int tid = threadIdx.x, lane = tid & 31, wid = tid >> 5;
    int warpM = wid >> 1, warpN = wid & 1;

    {
        int m = m0 + tid;
        rows_s[tid] = (m < cnt) ? g_tok[e * NTOK + m] : 0;
    }
    __syncthreads();

    uint32_t sbase = smem_u32(dsm);

    int arow = lane & 15;
    int akad = (lane >> 4) << 3;
    int brow = ((lane & 16) >> 1) | (lane & 7);
    int bkad = lane & 8;
    uint32_t a_off = (uint32_t)((warpM * 64 + arow) * SROWB + akad * 2);
    uint32_t b_off = (uint32_t)((warpN * 64 + brow) * SROWB + bkad * 2);

    float acc[4][8][4];
#pragma unroll
    for (int mt = 0; mt < 4; mt++)
#pragma unroll
        for (int nt = 0; nt < 8; nt++)
#pragma unroll
            for (int q = 0; q < 4; q++) acc[mt][nt][q] = 0.f;

    const int NC = DM / BK;   // 32

    auto load_stage = [&](int s, int k0) {
        uint32_t sb = sbase + s * STAGE_B;
#pragma unroll
        for (int j = 0; j < 4; j++) {
            int ci  = tid + j * 128;          // 0..511
            int row = ci >> 2, kc = ci & 3;
            uint32_t d0 = sb + row * SROWB + kc * 16;
            size_t ax = (size_t)rows_s[row] * DM + k0 + kc * 8;
            cpa16(d0,          g_x16 + ax);
            size_t bx = ((size_t)e * DE + n0 + row) * DM + k0 + kc * 8;
            cpa16(d0 + TILE_B, g_w1t + bx);
        }
    };

    load_stage(0, 0); CP_COMMIT();
    load_stage(1, BK); CP_COMMIT();

    for (int c = 0; c < NC; c++) {
        if (c + 2 < NC) load_stage((c + 2) & 3, (c + 2) * BK);
        CP_COMMIT();
        CP_WAIT2();
        __syncthreads();
        uint32_t sb = sbase + (c & 3) * STAGE_B;
#pragma unroll
        for (int ks = 0; ks < 2; ks++) { MMA_KSTEP(sb); }
    }

    // ---- epilogue: bias + gelu -> fp16 ----
    int r = lane >> 2, cp = (lane & 3) * 2;
#pragma unroll
    for (int mt = 0; mt < 4; mt++)
#pragma unroll
        for (int half = 0; half < 2; half++) {
            int m = m0 + warpM * 64 + mt * 16 + r + half * 8;
            if (m >= cnt) continue;
            size_t base = ((size_t)e * NTOK + m) * DE;
#pragma unroll
            for (int nt = 0; nt < 8; nt++) {
                int nn = n0 + warpN * 64 + nt * 8 + cp;
                float v0 = acc[mt][nt][half * 2 + 0] + b1[e * DE + nn];
                float v1 = acc[mt][nt][half * 2 + 1] + b1[e * DE + nn + 1];
                v0 = 0.5f * v0 * (1.0f + erff(v0 * 0.7071067811865476f));
                v1 = 0.5f * v1 * (1.0f + erff(v1 * 0.7071067811865476f));
                unsigned u = (unsigned)__half_as_ushort(__float2half_rn(v0)) |
                             ((unsigned)__half_as_ushort(__float2half_rn(v1)) << 16);
                *(unsigned*)((__half*)g_h16 + base + nn) = u;
            }
        }
}

// ============================================================
// 4) FF2: eo[e][slot] = h @ w2[e] + b2[e]   (plain stores)
// ============================================================
__global__ __launch_bounds__(128, 2) void ff2_mma(const float* __restrict__ b2) {
    extern __shared__ char dsm[];

    int e   = blockIdx.z;
    int cnt = g_count[e];
    int m0  = blockIdx.x * 128;
    if (m0 >= cnt) return;
    int n0  = blockIdx.y * 128;
    int tid = threadIdx.x, lane = tid & 31, wid = tid >> 5;
    int warpM = wid >> 1, warpN = wid & 1;

    uint32_t sbase = smem_u32(dsm);

    int arow = lane & 15;
    int akad = (lane >> 4) << 3;
    int brow = ((lane & 16) >> 1) | (lane & 7);
    int bkad = lane & 8;
    uint32_t a_off = (uint32_t)((warpM * 64 + arow) * SROWB + akad * 2);
    uint32_t b_off = (uint32_t)((warpN * 64 + brow) * SROWB + bkad * 2);

    float acc[4][8][4];
#pragma unroll
    for (int mt = 0; mt < 4; mt++)
#pragma unroll
        for (int nt = 0; nt < 8; nt++)
#pragma unroll
            for (int q = 0; q < 4; q++) acc[mt][nt][q] = 0.f;

    const int NC = DE / BK;   // 16

    auto load_stage = [&](int s, int k0) {
        uint32_t sb = sbase + s * STAGE_B;
#pragma unroll
        for (int j = 0; j < 4; j++) {
            int ci  = tid + j * 128;
            int row = ci >> 2, kc = ci & 3;
            uint32_t d0 = sb + row * SROWB + kc * 16;
            size_t ax = ((size_t)e * NTOK + m0 + row) * DE + k0 + kc * 8;
            cpa16(d0,          g_h16 + ax);
            size_t bx = ((size_t)e * DM + n0 + row) * DE + k0 + kc * 8;
            cpa16(d0 + TILE_B, g_w2t + bx);
        }
    };

    load_stage(0, 0); CP_COMMIT();
    load_stage(1, BK); CP_COMMIT();

    for (int c = 0; c < NC; c++) {
        if (c + 2 < NC) load_stage((c + 2) & 3, (c + 2) * BK);
        CP_COMMIT();
        CP_WAIT2();
        __syncthreads();
        uint32_t sb = sbase + (c & 3) * STAGE_B;
#pragma unroll
        for (int ks = 0; ks < 2; ks++) { MMA_KSTEP(sb); }
    }

    // ---- epilogue: eo = acc + b2 (plain stores) ----
    int r = lane >> 2, cp = (lane & 3) * 2;
#pragma unroll
    for (int mt = 0; mt < 4; mt++)
#pragma unroll
        for (int half = 0; half < 2; half++) {
            int m = m0 + warpM * 64 + mt * 16 + r + half * 8;
            if (m >= cnt) continue;
            float* erow = g_eo + ((size_t)e * NTOK + m) * DM;
#pragma unroll
            for (int nt = 0; nt < 8; nt++) {
                int nn = n0 + warpN * 64 + nt * 8 + cp;
                float v0 = acc[mt][nt][half * 2 + 0] + b2[e * DM + nn];
                float v1 = acc[mt][nt][half * 2 + 1] + b2[e * DM + nn + 1];
                *(float2*)(erow + nn) = make_float2(v0, v1);
            }
        }
}

// ============================================================
// 5) combine: out[tok] = g1*eo[loc1] + g2*eo[loc2]   (one warp/token)
// ============================================================
__global__ __launch_bounds__(256) void combine_kernel(float* __restrict__ out) {
    int tok  = (blockIdx.x * blockDim.x + threadIdx.x) >> 5;
    int lane = threadIdx.x & 31;
    if (tok >= NTOK) return;
    int loc1 = g_inv[2 * tok], loc2 = g_inv[2 * tok + 1];
    float g1 = g_gate[loc1], g2 = g_gate[loc2];
    const float4* e1 = (const float4*)(g_eo + (size_t)loc1 * DM);
    const float4* e2 = (const float4*)(g_eo + (size_t)loc2 * DM);
    float4* o = (float4*)(out + (size_t)tok * DM);
#pragma unroll
    for (int i = 0; i < 8; i++) {
        float4 a = e1[lane + i * 32];
        float4 b = e2[lane + i * 32];
        o[lane + i * 32] = make_float4(g1 * a.x + g2 * b.x, g1 * a.y + g2 * b.y,
                                       g1 * a.z + g2 * b.z, g1 * a.w + g2 * b.w);
    }
}

// ============================================================
// launcher: prep(side, t=0) || [init, route] ; join ; ff1, ff2, combine
// ============================================================
extern "C" void kernel_launch(void* const* d_in, const int* in_sizes, int n_in,
                              void* d_out, int out_size) {
    const float* x         = (const float*)d_in[0];
    const float* w1        = (const float*)d_in[1];
    const float* b1        = (const float*)d_in[2];
    const float* w2        = (const float*)d_in[3];
    const float* b2        = (const float*)d_in[4];
    const float* centroids = (const float*)d_in[5];
    const float* w_route   = (const float*)d_in[6];
    float* out = (float*)d_out;

    static cudaStream_t sA = nullptr;
    static cudaEvent_t evFork, evA;
    if (!sA) {
        cudaStreamCreateWithFlags(&sA, cudaStreamNonBlocking);
        cudaEventCreateWithFlags(&evFork, cudaEventDisableTiming);
        cudaEventCreateWithFlags(&evA, cudaEventDisableTiming);
        cudaFuncSetAttribute(ff1_mma, cudaFuncAttributeMaxDynamicSharedMemorySize, DYN_SMEM);
        cudaFuncSetAttribute(ff2_mma, cudaFuncAttributeMaxDynamicSharedMemorySize, DYN_SMEM);
    }

    cudaEventRecord(evFork, 0);
    cudaStreamWaitEvent(sA, evFork, 0);
    prep_all<<<XB + 8192, 256, 0, sA>>>(x, w1, w2);
    cudaEventRecord(evA, sA);

    init_kernel<<<1, 256>>>(centroids);
    route_kernel<<<NTOK / 4, 128>>>(x, centroids, w_route);

    cudaStreamWaitEvent(0, evA, 0);
    ff1_mma<<<dim3(NTOK / 128, DE / 128, NE), 128, DYN_SMEM>>>(b1);
    ff2_mma<<<dim3(NTOK / 128, DM / 128, NE), 128, DYN_SMEM>>>(b2);
    combine_kernel<<<NTOK / 8, 256>>>(out);
}